// round 6
// baseline (speedup 1.0000x reference)
#include <cuda_runtime.h>
#include <cuda_bf16.h>
#include <cstdint>

#define NROWS 8192
#define NCODES 8192
#define HID 256
#define EPS 0.5f
#define CAP 192

typedef unsigned long long u64;

// ---------------------------------------------------------------------------
// Device scratch (static globals — allocation-free)
// ---------------------------------------------------------------------------
__device__ __align__(16) __nv_bfloat16 g_hbf[NROWS * HID];
__device__ __align__(16) __nv_bfloat16 g_cbf[NCODES * HID];
__device__ float g_hsq[NROWS];
__device__ float g_csq[NCODES];
__device__ __align__(16) u64 g_cand[(size_t)NROWS * CAP];   // ~12.6 MB
__device__ int g_ccount[NROWS];

__device__ __forceinline__ uint32_t smem_u32(const void* p) {
    uint32_t a;
    asm("{ .reg .u64 t; cvta.to.shared.u64 t, %1; cvt.u32.u64 %0, t; }"
        : "=r"(a) : "l"(p));
    return a;
}
__device__ __forceinline__ void cp16(uint32_t dst, const void* src) {
    asm volatile("cp.async.cg.shared.global [%0], [%1], 16;" :: "r"(dst), "l"(src));
}
#define CP_COMMIT() asm volatile("cp.async.commit_group;" ::: "memory")
#define CP_WAIT0()  asm volatile("cp.async.wait_group 0;"  ::: "memory")

#define LDSM_X4(r0, r1, r2, r3, addr)                                          \
    asm volatile("ldmatrix.sync.aligned.m8n8.x4.shared.b16 {%0,%1,%2,%3}, [%4];" \
                 : "=r"(r0), "=r"(r1), "=r"(r2), "=r"(r3) : "r"(addr))

#define MMA16816(d, a0, a1, a2, a3, b0, b1)                                    \
    asm volatile(                                                              \
        "mma.sync.aligned.m16n8k16.row.col.f32.bf16.bf16.f32 "                 \
        "{%0,%1,%2,%3}, {%4,%5,%6,%7}, {%8,%9}, {%0,%1,%2,%3};"                \
        : "+f"((d)[0]), "+f"((d)[1]), "+f"((d)[2]), "+f"((d)[3])               \
        : "r"(a0), "r"(a1), "r"(a2), "r"(a3), "r"(b0), "r"(b1))

// order-preserving float<->uint map
__device__ __forceinline__ unsigned enc_f(float f) {
    unsigned u = __float_as_uint(f);
    return (u & 0x80000000u) ? ~u : (u | 0x80000000u);
}
__device__ __forceinline__ float dec_f(unsigned e) {
    unsigned u = (e & 0x80000000u) ? (e ^ 0x80000000u) : ~e;
    return __uint_as_float(u);
}

// ---------------------------------------------------------------------------
// Fused fp32->bf16 convert + squared norms (one warp per row) + counter reset
// ---------------------------------------------------------------------------
__global__ void convert_norms_kernel(const float* __restrict__ h,
                                     const float* __restrict__ cb) {
    if (blockIdx.x < NROWS / 256)
        g_ccount[blockIdx.x * 256 + threadIdx.x] = 0;

    int warp = (blockIdx.x * blockDim.x + threadIdx.x) >> 5;
    int lane = threadIdx.x & 31;
    const float* src;
    __nv_bfloat16* dst;
    float* nrm;
    if (warp < NROWS) {
        src = h + (size_t)warp * HID; dst = g_hbf + (size_t)warp * HID; nrm = &g_hsq[warp];
    } else {
        int r = warp - NROWS;
        if (r >= NCODES) return;
        src = cb + (size_t)r * HID; dst = g_cbf + (size_t)r * HID; nrm = &g_csq[r];
    }
    float s = 0.f;
#pragma unroll
    for (int half2i = 0; half2i < 2; ++half2i) {
        float4 a = ((const float4*)src)[lane + half2i * 32];
        s = fmaf(a.x, a.x, s); s = fmaf(a.y, a.y, s);
        s = fmaf(a.z, a.z, s); s = fmaf(a.w, a.w, s);
        __nv_bfloat162 p0 = __floats2bfloat162_rn(a.x, a.y);
        __nv_bfloat162 p1 = __floats2bfloat162_rn(a.z, a.w);
        uint2 w;
        w.x = *reinterpret_cast<uint32_t*>(&p0);
        w.y = *reinterpret_cast<uint32_t*>(&p1);
        ((uint2*)dst)[lane + half2i * 32] = w;
    }
#pragma unroll
    for (int o = 16; o; o >>= 1) s += __shfl_xor_sync(0xFFFFFFFFu, s, o);
    if (lane == 0) *nrm = s;
}

// ---------------------------------------------------------------------------
// Strip-mined bf16 HMMA GEMM + fused argmin-candidate epilogue + out zeroing.
// 128 CTAs: CTA = (row_block rb = bx>>1) x (col half = bx&1, 4096 cols).
// A tile resident; B double-buffered via cp.async; 32 col-blocks of 128.
// ---------------------------------------------------------------------------
#define ROW_STRIDE 528               // 512B data + 16B pad (conflict-free ldmatrix)
#define TILE_BYTES (128 * ROW_STRIDE)          // 67584
#define SM_TOTAL (3 * TILE_BYTES + 512)        // A + 2xB + rowmin

__global__ __launch_bounds__(256, 1) void vq_gemm_kernel(float* __restrict__ out) {
    extern __shared__ char smem[];
    const uint32_t sb = smem_u32(smem);
    const int tid = threadIdx.x;
    const int lane = tid & 31;
    const int wid = tid >> 5;
    const int wm = wid & 1;          // warp row (2 x 64)
    const int wn = wid >> 1;         // warp col (4 x 32)
    const int rb = blockIdx.x >> 1;
    const int chf = blockIdx.x & 1;
    const int row0 = rb * 128;

    const uint32_t smA  = sb;
    const uint32_t smB0 = sb + TILE_BYTES;
    const uint32_t smB1 = sb + 2 * TILE_BYTES;
    unsigned* rowmin = (unsigned*)(smem + 3 * TILE_BYTES);

    // Prefetch A (row block) + B block 0 in one cp.async group
    {
        const char* asrc = (const char*)(g_hbf + (size_t)row0 * HID);
        const char* bsrc = (const char*)(g_cbf + (size_t)(chf * 4096) * HID);
#pragma unroll
        for (int i = 0; i < 16; ++i) {
            int idx = tid + i * 256;
            int r = idx >> 5, c = idx & 31;
            cp16(smA  + r * ROW_STRIDE + c * 16, asrc + r * 512 + c * 16);
            cp16(smB0 + r * ROW_STRIDE + c * 16, bsrc + r * 512 + c * 16);
        }
        CP_COMMIT();
    }

    float acc[4][4][4];
#pragma unroll
    for (int mi = 0; mi < 4; ++mi)
#pragma unroll
        for (int ni = 0; ni < 4; ++ni)
#pragma unroll
            for (int q = 0; q < 4; ++q) acc[mi][ni][q] = 0.f;

    const int lrow = lane & 15;
    const int lkc  = lane >> 4;

    for (int cbk = 0; cbk < 32; ++cbk) {
        CP_WAIT0();
        __syncthreads();   // current B buf ready; all warps past previous iter

        // prefetch next B block (overwrites buf used two iters ago — safe)
        if (cbk + 1 < 32) {
            const char* bsrc =
                (const char*)(g_cbf + (size_t)(chf * 4096 + (cbk + 1) * 128) * HID);
            const uint32_t dstb = ((cbk + 1) & 1) ? smB1 : smB0;
#pragma unroll
            for (int i = 0; i < 16; ++i) {
                int idx = tid + i * 256;
                int r = idx >> 5, c = idx & 31;
                cp16(dstb + r * ROW_STRIDE + c * 16, bsrc + r * 512 + c * 16);
            }
            CP_COMMIT();
        }

        // ---- MMA mainloop on current block ----
        const uint32_t smB = (cbk & 1) ? smB1 : smB0;
        const uint32_t aAddr0 = smA + (wm * 64 + lrow) * ROW_STRIDE + lkc * 16;
        const uint32_t bAddr0 = smB + (wn * 32 + lrow) * ROW_STRIDE + lkc * 16;
#pragma unroll 4
        for (int ks = 0; ks < 16; ++ks) {
            const uint32_t koff = (uint32_t)ks * 32;
            uint32_t a[4][4], b[2][4];
#pragma unroll
            for (int mi = 0; mi < 4; ++mi)
                LDSM_X4(a[mi][0], a[mi][1], a[mi][2], a[mi][3],
                        aAddr0 + mi * 16 * ROW_STRIDE + koff);
#pragma unroll
            for (int nj = 0; nj < 2; ++nj)
                LDSM_X4(b[nj][0], b[nj][1], b[nj][2], b[nj][3],
                        bAddr0 + nj * 16 * ROW_STRIDE + koff);
#pragma unroll
            for (int mi = 0; mi < 4; ++mi) {
#pragma unroll
                for (int nj = 0; nj < 2; ++nj) {
                    MMA16816(acc[mi][2 * nj],     a[mi][0], a[mi][1], a[mi][2], a[mi][3],
                             b[nj][0], b[nj][2]);
                    MMA16816(acc[mi][2 * nj + 1], a[mi][0], a[mi][1], a[mi][2], a[mi][3],
                             b[nj][1], b[nj][3]);
                }
            }
        }

        // ---- fused epilogue: scores, per-row block min, candidate push ----
        if (tid < 128) rowmin[tid] = 0xFFFFFFFFu;
        __syncthreads();

        const int col0 = chf * 4096 + cbk * 128;
        float2 csq2[4];
#pragma unroll
        for (int ni = 0; ni < 4; ++ni)
            csq2[ni] = *(const float2*)&g_csq[col0 + wn * 32 + ni * 8 + 2 * (lane & 3)];

        // in-place: acc <- score = csq - 2*dot
#pragma unroll
        for (int mi = 0; mi < 4; ++mi)
#pragma unroll
            for (int ni = 0; ni < 4; ++ni) {
                acc[mi][ni][0] = csq2[ni].x - 2.0f * acc[mi][ni][0];
                acc[mi][ni][1] = csq2[ni].y - 2.0f * acc[mi][ni][1];
                acc[mi][ni][2] = csq2[ni].x - 2.0f * acc[mi][ni][2];
                acc[mi][ni][3] = csq2[ni].y - 2.0f * acc[mi][ni][3];
            }

        // per-row min across this warp's 32 cols (quad shuffle), then smem
#pragma unroll
        for (int mi = 0; mi < 4; ++mi)
#pragma unroll
            for (int hh = 0; hh < 2; ++hh) {
                float m = acc[mi][0][2 * hh];
#pragma unroll
                for (int ni = 0; ni < 4; ++ni) {
                    m = fminf(m, acc[mi][ni][2 * hh]);
                    m = fminf(m, acc[mi][ni][2 * hh + 1]);
                }
                m = fminf(m, __shfl_xor_sync(0xFFFFFFFFu, m, 1));
                m = fminf(m, __shfl_xor_sync(0xFFFFFFFFu, m, 2));
                if ((lane & 3) == 0)
                    atomicMin(&rowmin[wm * 64 + mi * 16 + (lane >> 2) + hh * 8], enc_f(m));
            }
        __syncthreads();

        // push candidates within EPS of block-local row min
#pragma unroll
        for (int mi = 0; mi < 4; ++mi)
#pragma unroll
            for (int hh = 0; hh < 2; ++hh) {
                const int rloc = wm * 64 + mi * 16 + (lane >> 2) + hh * 8;
                const float thr = dec_f(rowmin[rloc]) + EPS;
                const int grow = row0 + rloc;
#pragma unroll
                for (int ni = 0; ni < 4; ++ni)
#pragma unroll
                    for (int q2 = 0; q2 < 2; ++q2) {
                        float v = acc[mi][ni][2 * hh + q2];
                        if (v < thr) {
                            int col = col0 + wn * 32 + ni * 8 + 2 * (lane & 3) + q2;
                            int p = atomicAdd(&g_ccount[grow], 1);
                            if (p < CAP)
                                g_cand[(size_t)grow * CAP + p] =
                                    ((u64)enc_f(v) << 32) | (unsigned)col;
                        }
                    }
            }

        // reset accumulators
#pragma unroll
        for (int mi = 0; mi < 4; ++mi)
#pragma unroll
            for (int ni = 0; ni < 4; ++ni)
#pragma unroll
                for (int q = 0; q < 4; ++q) acc[mi][ni][q] = 0.f;

        // ---- zero this CTA's 128x128 output chunk (hidden under compute) ----
        float* obase = out + (size_t)row0 * NCODES + col0;
#pragma unroll
        for (int i = 0; i < 16; ++i) {
            int idx = tid + i * 256;
            int r = idx >> 5, c = idx & 31;
            *(uint4*)(obase + (size_t)r * NCODES + c * 4) = make_uint4(0, 0, 0, 0);
        }
    }
}

// ---------------------------------------------------------------------------
// Select: 1 warp per row. Scan candidate list (<=CAP entries), global approx
// min, exact fp32 rescore of entries within EPS, one-hot + loss.
// ---------------------------------------------------------------------------
__global__ __launch_bounds__(256) void select_kernel(const float* __restrict__ h,
                                                     const float* __restrict__ cbp,
                                                     float* __restrict__ out) {
    const int row = blockIdx.x * 8 + (threadIdx.x >> 5);
    const int lane = threadIdx.x & 31;
    const unsigned FULL = 0xFFFFFFFFu;

    const int n = min(g_ccount[row], CAP);
    const u64* lst = &g_cand[(size_t)row * CAP];

    u64 bmin = 0xFFFFFFFFFFFFFFFFull;
    for (int i = lane; i < n; i += 32) bmin = min(bmin, lst[i]);
#pragma unroll
    for (int o = 16; o; o >>= 1) {
        u64 t = __shfl_xor_sync(FULL, bmin, o);
        if (t < bmin) bmin = t;
    }
    const float thr = dec_f((unsigned)(bmin >> 32)) + EPS;
    const float hsq = g_hsq[row];
    const float4* hp = (const float4*)(h + (size_t)row * HID);
    const float4 ha = hp[lane * 2];
    const float4 hb = hp[lane * 2 + 1];

    u64 bestkey = 0xFFFFFFFFFFFFFFFFull;
    for (int base = 0; base < n; base += 32) {
        int i = base + lane;
        u64 e = (i < n) ? lst[i] : 0xFFFFFFFFFFFFFFFFull;
        bool ok = (i < n) && (dec_f((unsigned)(e >> 32)) < thr);
        unsigned mask = __ballot_sync(FULL, ok);
        while (mask) {
            int j = __ffs(mask) - 1;
            mask &= mask - 1;
            unsigned col = __shfl_sync(FULL, (unsigned)(e & 0xFFFFFFFFull), j);
            const float4* cp = (const float4*)(cbp + (size_t)col * HID);
            float4 ca = cp[lane * 2];
            float4 cbv = cp[lane * 2 + 1];
            float d = 0.f;
            d = fmaf(ha.x, ca.x, d);  d = fmaf(ha.y, ca.y, d);
            d = fmaf(ha.z, ca.z, d);  d = fmaf(ha.w, ca.w, d);
            d = fmaf(hb.x, cbv.x, d); d = fmaf(hb.y, cbv.y, d);
            d = fmaf(hb.z, cbv.z, d); d = fmaf(hb.w, cbv.w, d);
#pragma unroll
            for (int o = 16; o; o >>= 1) d += __shfl_xor_sync(FULL, d, o);
            float s = __fadd_rn(__fsub_rn(hsq, __fmul_rn(2.0f, d)), g_csq[col]);
            u64 key = ((u64)enc_f(s) << 32) | col;
            if (key < bestkey) bestkey = key;
        }
    }

    const unsigned idx = (unsigned)(bestkey & 0xFFFFFFFFull);
    const float4* cp = (const float4*)(cbp + (size_t)idx * HID);
    float4 ca = cp[lane * 2];
    float4 cbv = cp[lane * 2 + 1];
    float s = 0.f;
    float d;
    d = ha.x - ca.x;  s = fmaf(d, d, s);  d = ha.y - ca.y;  s = fmaf(d, d, s);
    d = ha.z - ca.z;  s = fmaf(d, d, s);  d = ha.w - ca.w;  s = fmaf(d, d, s);
    d = hb.x - cbv.x; s = fmaf(d, d, s);  d = hb.y - cbv.y; s = fmaf(d, d, s);
    d = hb.z - cbv.z; s = fmaf(d, d, s);  d = hb.w - cbv.w; s = fmaf(d, d, s);
#pragma unroll
    for (int o = 16; o; o >>= 1) s += __shfl_xor_sync(FULL, s, o);

    if (lane == 0) {
        out[(size_t)row * NCODES + idx] = 1.0f;
        float m = s * (1.0f / (float)HID);
        out[(size_t)NROWS * NCODES + row] = __fadd_rn(m, __fmul_rn(0.25f, m));
    }
}

// ---------------------------------------------------------------------------
extern "C" void kernel_launch(void* const* d_in, const int* in_sizes, int n_in,
                              void* d_out, int out_size) {
    const float* h  = (const float*)d_in[0];   // (8192, 256)
    const float* cb = (const float*)d_in[2];   // (8192, 256)
    float* out = (float*)d_out;

    static bool attr_set = false;
    if (!attr_set) {
        cudaFuncSetAttribute(vq_gemm_kernel,
                             cudaFuncAttributeMaxDynamicSharedMemorySize, SM_TOTAL);
        attr_set = true;
    }

    convert_norms_kernel<<<(NROWS + NCODES) / 8, 256>>>(h, cb);
    vq_gemm_kernel<<<128, 256, SM_TOTAL>>>(out);
    select_kernel<<<NROWS / 8, 256>>>(h, cb, out);
}

// round 7
// speedup vs baseline: 1.3085x; 1.3085x over previous
#include <cuda_runtime.h>
#include <cuda_bf16.h>
#include <cstdint>

#define NROWS 8192
#define NCODES 8192
#define HID 256
#define EPS 0.5f
#define CAP 192

typedef unsigned long long u64;

// ---------------------------------------------------------------------------
// Device scratch (static globals — allocation-free)
// ---------------------------------------------------------------------------
__device__ __align__(16) __nv_bfloat16 g_hbf[NROWS * HID];
__device__ __align__(16) __nv_bfloat16 g_cbf[NCODES * HID];
__device__ float g_hsq[NROWS];
__device__ float g_csq[NCODES];
__device__ __align__(16) u64 g_cand[(size_t)NROWS * CAP];   // ~12.6 MB
__device__ int g_ccount[NROWS];

__device__ __forceinline__ uint32_t smem_u32(const void* p) {
    uint32_t a;
    asm("{ .reg .u64 t; cvta.to.shared.u64 t, %1; cvt.u32.u64 %0, t; }"
        : "=r"(a) : "l"(p));
    return a;
}
__device__ __forceinline__ void cp16(uint32_t dst, const void* src) {
    asm volatile("cp.async.cg.shared.global [%0], [%1], 16;" :: "r"(dst), "l"(src));
}
#define CP_COMMIT() asm volatile("cp.async.commit_group;" ::: "memory")
#define CP_WAIT0()  asm volatile("cp.async.wait_group 0;"  ::: "memory")

#define LDSM_X4(r0, r1, r2, r3, addr)                                          \
    asm volatile("ldmatrix.sync.aligned.m8n8.x4.shared.b16 {%0,%1,%2,%3}, [%4];" \
                 : "=r"(r0), "=r"(r1), "=r"(r2), "=r"(r3) : "r"(addr))

#define MMA16816(d, a0, a1, a2, a3, b0, b1)                                    \
    asm volatile(                                                              \
        "mma.sync.aligned.m16n8k16.row.col.f32.bf16.bf16.f32 "                 \
        "{%0,%1,%2,%3}, {%4,%5,%6,%7}, {%8,%9}, {%0,%1,%2,%3};"                \
        : "+f"((d)[0]), "+f"((d)[1]), "+f"((d)[2]), "+f"((d)[3])               \
        : "r"(a0), "r"(a1), "r"(a2), "r"(a3), "r"(b0), "r"(b1))

// order-preserving float<->uint map
__device__ __forceinline__ unsigned enc_f(float f) {
    unsigned u = __float_as_uint(f);
    return (u & 0x80000000u) ? ~u : (u | 0x80000000u);
}
__device__ __forceinline__ float dec_f(unsigned e) {
    unsigned u = (e & 0x80000000u) ? (e ^ 0x80000000u) : ~e;
    return __uint_as_float(u);
}

// ---------------------------------------------------------------------------
// Fused fp32->bf16 convert + squared norms (one warp per row) + counter reset
// ---------------------------------------------------------------------------
__global__ void convert_norms_kernel(const float* __restrict__ h,
                                     const float* __restrict__ cb) {
    if (blockIdx.x < NROWS / 256)
        g_ccount[blockIdx.x * 256 + threadIdx.x] = 0;

    int warp = (blockIdx.x * blockDim.x + threadIdx.x) >> 5;
    int lane = threadIdx.x & 31;
    const float* src;
    __nv_bfloat16* dst;
    float* nrm;
    if (warp < NROWS) {
        src = h + (size_t)warp * HID; dst = g_hbf + (size_t)warp * HID; nrm = &g_hsq[warp];
    } else {
        int r = warp - NROWS;
        if (r >= NCODES) return;
        src = cb + (size_t)r * HID; dst = g_cbf + (size_t)r * HID; nrm = &g_csq[r];
    }
    float s = 0.f;
#pragma unroll
    for (int half2i = 0; half2i < 2; ++half2i) {
        float4 a = ((const float4*)src)[lane + half2i * 32];
        s = fmaf(a.x, a.x, s); s = fmaf(a.y, a.y, s);
        s = fmaf(a.z, a.z, s); s = fmaf(a.w, a.w, s);
        __nv_bfloat162 p0 = __floats2bfloat162_rn(a.x, a.y);
        __nv_bfloat162 p1 = __floats2bfloat162_rn(a.z, a.w);
        uint2 w;
        w.x = *reinterpret_cast<uint32_t*>(&p0);
        w.y = *reinterpret_cast<uint32_t*>(&p1);
        ((uint2*)dst)[lane + half2i * 32] = w;
    }
#pragma unroll
    for (int o = 16; o; o >>= 1) s += __shfl_xor_sync(0xFFFFFFFFu, s, o);
    if (lane == 0) *nrm = s;
}

// ---------------------------------------------------------------------------
// bf16 HMMA GEMM: one 128x128 tile per CTA (4096 CTAs), K=256 staged once.
// Fused epilogue: per-row block min -> candidate push -> zero out-chunk.
// No score materialization, no separate memset.
// ---------------------------------------------------------------------------
#define ROW_STRIDE 528               // 512B data + 16B pad (conflict-free ldmatrix)
#define TILE_BYTES (128 * ROW_STRIDE)
#define SM_A 0
#define SM_B TILE_BYTES
#define SM_TOTAL (2 * TILE_BYTES + 512)

__global__ __launch_bounds__(256, 1) void vq_gemm_kernel(float* __restrict__ out) {
    extern __shared__ char smem[];
    const uint32_t sb = smem_u32(smem);
    const int tid = threadIdx.x;
    const int lane = tid & 31;
    const int wid = tid >> 5;
    const int wm = wid & 1;          // warp row (2 x 64)
    const int wn = wid >> 1;         // warp col (4 x 32)
    const int row0 = blockIdx.y * 128;
    const int col0 = blockIdx.x * 128;
    unsigned* rowmin = (unsigned*)(smem + 2 * TILE_BYTES);

    // --- Stage A (h rows) and B (code rows) via cp.async: 128 rows x 512B each
    {
        const char* asrc = (const char*)(g_hbf + (size_t)row0 * HID);
        const char* bsrc = (const char*)(g_cbf + (size_t)col0 * HID);
#pragma unroll
        for (int i = 0; i < 16; ++i) {
            int idx = tid + i * 256;
            int r = idx >> 5, c = idx & 31;
            cp16(sb + SM_A + r * ROW_STRIDE + c * 16, asrc + r * 512 + c * 16);
            cp16(sb + SM_B + r * ROW_STRIDE + c * 16, bsrc + r * 512 + c * 16);
        }
        CP_COMMIT();
    }
    if (tid < 128) rowmin[tid] = 0xFFFFFFFFu;

    float acc[4][4][4];              // [mi][ni][reg]
#pragma unroll
    for (int mi = 0; mi < 4; ++mi)
#pragma unroll
        for (int ni = 0; ni < 4; ++ni)
#pragma unroll
            for (int q = 0; q < 4; ++q) acc[mi][ni][q] = 0.f;

    CP_WAIT0();
    __syncthreads();

    // --- Mainloop: 16 K-steps of k16 ---
    const int lrow = lane & 15;
    const int lkc  = lane >> 4;
    const uint32_t aAddr0 = sb + SM_A + (wm * 64 + lrow) * ROW_STRIDE + lkc * 16;
    const uint32_t bAddr0 = sb + SM_B + (wn * 32 + lrow) * ROW_STRIDE + lkc * 16;

#pragma unroll 4
    for (int ks = 0; ks < 16; ++ks) {
        const uint32_t koff = (uint32_t)ks * 32;
        uint32_t a[4][4], b[2][4];
#pragma unroll
        for (int mi = 0; mi < 4; ++mi)
            LDSM_X4(a[mi][0], a[mi][1], a[mi][2], a[mi][3],
                    aAddr0 + mi * 16 * ROW_STRIDE + koff);
#pragma unroll
        for (int nj = 0; nj < 2; ++nj)
            LDSM_X4(b[nj][0], b[nj][1], b[nj][2], b[nj][3],
                    bAddr0 + nj * 16 * ROW_STRIDE + koff);
#pragma unroll
        for (int mi = 0; mi < 4; ++mi) {
#pragma unroll
            for (int nj = 0; nj < 2; ++nj) {
                MMA16816(acc[mi][2 * nj],     a[mi][0], a[mi][1], a[mi][2], a[mi][3],
                         b[nj][0], b[nj][2]);
                MMA16816(acc[mi][2 * nj + 1], a[mi][0], a[mi][1], a[mi][2], a[mi][3],
                         b[nj][1], b[nj][3]);
            }
        }
    }

    // --- Epilogue: score = csq - 2*dot (in place) ---
    float2 csq2[4];
#pragma unroll
    for (int ni = 0; ni < 4; ++ni)
        csq2[ni] = *(const float2*)&g_csq[col0 + wn * 32 + ni * 8 + 2 * (lane & 3)];
#pragma unroll
    for (int mi = 0; mi < 4; ++mi)
#pragma unroll
        for (int ni = 0; ni < 4; ++ni) {
            acc[mi][ni][0] = csq2[ni].x - 2.0f * acc[mi][ni][0];
            acc[mi][ni][1] = csq2[ni].y - 2.0f * acc[mi][ni][1];
            acc[mi][ni][2] = csq2[ni].x - 2.0f * acc[mi][ni][2];
            acc[mi][ni][3] = csq2[ni].y - 2.0f * acc[mi][ni][3];
        }

    // per-row min across warp's 32 cols (quad shuffle) -> smem atomicMin
#pragma unroll
    for (int mi = 0; mi < 4; ++mi)
#pragma unroll
        for (int hh = 0; hh < 2; ++hh) {
            float m = acc[mi][0][2 * hh];
#pragma unroll
            for (int ni = 0; ni < 4; ++ni) {
                m = fminf(m, acc[mi][ni][2 * hh]);
                m = fminf(m, acc[mi][ni][2 * hh + 1]);
            }
            m = fminf(m, __shfl_xor_sync(0xFFFFFFFFu, m, 1));
            m = fminf(m, __shfl_xor_sync(0xFFFFFFFFu, m, 2));
            if ((lane & 3) == 0)
                atomicMin(&rowmin[wm * 64 + mi * 16 + (lane >> 2) + hh * 8], enc_f(m));
        }
    __syncthreads();

    // push candidates within EPS of block-local row min
#pragma unroll
    for (int mi = 0; mi < 4; ++mi)
#pragma unroll
        for (int hh = 0; hh < 2; ++hh) {
            const int rloc = wm * 64 + mi * 16 + (lane >> 2) + hh * 8;
            const float thr = dec_f(rowmin[rloc]) + EPS;
            const int grow = row0 + rloc;
#pragma unroll
            for (int ni = 0; ni < 4; ++ni)
#pragma unroll
                for (int q2 = 0; q2 < 2; ++q2) {
                    float v = acc[mi][ni][2 * hh + q2];
                    if (v < thr) {
                        int col = col0 + wn * 32 + ni * 8 + 2 * (lane & 3) + q2;
                        int p = atomicAdd(&g_ccount[grow], 1);
                        if (p < CAP)
                            g_cand[(size_t)grow * CAP + p] =
                                ((u64)enc_f(v) << 32) | (unsigned)col;
                    }
                }
        }

    // --- Zero this CTA's 128x128 output chunk ---
    float* obase = out + (size_t)row0 * NCODES + col0;
#pragma unroll
    for (int i = 0; i < 16; ++i) {
        int idx = tid + i * 256;
        int r = idx >> 5, c = idx & 31;
        *(uint4*)(obase + (size_t)r * NCODES + c * 4) = make_uint4(0, 0, 0, 0);
    }
}

// ---------------------------------------------------------------------------
// Select: 1 warp per row. Scan candidate list (<=CAP), global approx min,
// exact fp32 rescore of entries within EPS, one-hot + loss.
// ---------------------------------------------------------------------------
__global__ __launch_bounds__(256) void select_kernel(const float* __restrict__ h,
                                                     const float* __restrict__ cbp,
                                                     float* __restrict__ out) {
    const int row = blockIdx.x * 8 + (threadIdx.x >> 5);
    const int lane = threadIdx.x & 31;
    const unsigned FULL = 0xFFFFFFFFu;

    const int n = min(g_ccount[row], CAP);
    const u64* lst = &g_cand[(size_t)row * CAP];

    u64 bmin = 0xFFFFFFFFFFFFFFFFull;
    for (int i = lane; i < n; i += 32) bmin = min(bmin, lst[i]);
#pragma unroll
    for (int o = 16; o; o >>= 1) {
        u64 t = __shfl_xor_sync(FULL, bmin, o);
        if (t < bmin) bmin = t;
    }
    const float thr = dec_f((unsigned)(bmin >> 32)) + EPS;
    const float hsq = g_hsq[row];
    const float4* hp = (const float4*)(h + (size_t)row * HID);
    const float4 ha = hp[lane * 2];
    const float4 hb = hp[lane * 2 + 1];

    u64 bestkey = 0xFFFFFFFFFFFFFFFFull;
    for (int base = 0; base < n; base += 32) {
        int i = base + lane;
        u64 e = (i < n) ? lst[i] : 0xFFFFFFFFFFFFFFFFull;
        bool ok = (i < n) && (dec_f((unsigned)(e >> 32)) < thr);
        unsigned mask = __ballot_sync(FULL, ok);
        while (mask) {
            int j = __ffs(mask) - 1;
            mask &= mask - 1;
            unsigned col = __shfl_sync(FULL, (unsigned)(e & 0xFFFFFFFFull), j);
            const float4* cp = (const float4*)(cbp + (size_t)col * HID);
            float4 ca = cp[lane * 2];
            float4 cbv = cp[lane * 2 + 1];
            float d = 0.f;
            d = fmaf(ha.x, ca.x, d);  d = fmaf(ha.y, ca.y, d);
            d = fmaf(ha.z, ca.z, d);  d = fmaf(ha.w, ca.w, d);
            d = fmaf(hb.x, cbv.x, d); d = fmaf(hb.y, cbv.y, d);
            d = fmaf(hb.z, cbv.z, d); d = fmaf(hb.w, cbv.w, d);
#pragma unroll
            for (int o = 16; o; o >>= 1) d += __shfl_xor_sync(FULL, d, o);
            float s = __fadd_rn(__fsub_rn(hsq, __fmul_rn(2.0f, d)), g_csq[col]);
            u64 key = ((u64)enc_f(s) << 32) | col;
            if (key < bestkey) bestkey = key;
        }
    }

    const unsigned idx = (unsigned)(bestkey & 0xFFFFFFFFull);
    const float4* cp = (const float4*)(cbp + (size_t)idx * HID);
    float4 ca = cp[lane * 2];
    float4 cbv = cp[lane * 2 + 1];
    float s = 0.f;
    float d;
    d = ha.x - ca.x;  s = fmaf(d, d, s);  d = ha.y - ca.y;  s = fmaf(d, d, s);
    d = ha.z - ca.z;  s = fmaf(d, d, s);  d = ha.w - ca.w;  s = fmaf(d, d, s);
    d = hb.x - cbv.x; s = fmaf(d, d, s);  d = hb.y - cbv.y; s = fmaf(d, d, s);
    d = hb.z - cbv.z; s = fmaf(d, d, s);  d = hb.w - cbv.w; s = fmaf(d, d, s);
#pragma unroll
    for (int o = 16; o; o >>= 1) s += __shfl_xor_sync(FULL, s, o);

    if (lane == 0) {
        out[(size_t)row * NCODES + idx] = 1.0f;
        float m = s * (1.0f / (float)HID);
        out[(size_t)NROWS * NCODES + row] = __fadd_rn(m, __fmul_rn(0.25f, m));
    }
}

// ---------------------------------------------------------------------------
extern "C" void kernel_launch(void* const* d_in, const int* in_sizes, int n_in,
                              void* d_out, int out_size) {
    const float* h  = (const float*)d_in[0];   // (8192, 256)
    const float* cb = (const float*)d_in[2];   // (8192, 256)
    float* out = (float*)d_out;

    static bool attr_set = false;
    if (!attr_set) {
        cudaFuncSetAttribute(vq_gemm_kernel,
                             cudaFuncAttributeMaxDynamicSharedMemorySize, SM_TOTAL);
        attr_set = true;
    }

    convert_norms_kernel<<<(NROWS + NCODES) / 8, 256>>>(h, cb);

    dim3 grid(NCODES / 128, NROWS / 128);  // (64, 64)
    vq_gemm_kernel<<<grid, 256, SM_TOTAL>>>(out);

    select_kernel<<<NROWS / 8, 256>>>(h, cb, out);
}